// round 1
// baseline (speedup 1.0000x reference)
#include <cuda_runtime.h>
#include <math.h>

// Model constants
constexpr int CD  = 768;     // model dim
constexpr int CS  = 1024;    // seq len
constexpr int CB  = 2;       // batch
constexpr int CM  = CB * CS; // 2048 rows
constexpr int CH  = 12;      // heads
constexpr int CHD = 64;      // head dim
constexpr int CL  = 6;       // layers
constexpr int CF  = 3072;    // ffn dim
constexpr int CV  = 32000;   // vocab

// Scratch (device globals — no allocation allowed)
__device__ float g_x  [CM * CD];
__device__ float g_q  [CM * CD];
__device__ float g_k  [CM * CD];
__device__ float g_v  [CM * CD];
__device__ float g_att[CM * CD];
__device__ float g_ff [CM * CF];

// ---------------------------------------------------------------------------
// Embedding: x = emb[ids] * sqrt(D) + pe[s]
// ---------------------------------------------------------------------------
__global__ void embed_kernel(const int* __restrict__ ids, const float* __restrict__ emb,
                             const float* __restrict__ pe, float* __restrict__ out) {
    int idx = blockIdx.x * blockDim.x + threadIdx.x;
    if (idx >= CM * CD) return;
    int r = idx / CD;
    int d = idx - r * CD;
    int s = r & (CS - 1);
    out[idx] = emb[ids[r] * CD + d] * 27.712812921102035f + pe[s * CD + d];
}

// ---------------------------------------------------------------------------
// Tiled fp32 GEMM: C[M,N] = A[M,K] @ B[K,N] + bias[N]  (ACT=1 -> exact GELU)
// 64x64 tile, BK=16, 256 threads, 4x4 micro-tile. All dims multiple of 64/16.
// ---------------------------------------------------------------------------
template <int ACT>
__global__ void gemm_kernel(const float* __restrict__ A, const float* __restrict__ B,
                            const float* __restrict__ bias, float* __restrict__ C,
                            int Mq, int N, int K) {
    __shared__ float As[16][64];
    __shared__ float Bs[16][68];
    int t  = threadIdx.x;
    int tx = t & 15, ty = t >> 4;
    int r0 = blockIdx.y * 64, c0 = blockIdx.x * 64;

    int ai = t >> 2, ak = (t & 3) << 2;   // A loader: row ai, k-offset ak
    int bk = t >> 4, bj = (t & 15) << 2;  // B loader: k-row bk, col-offset bj

    float acc[4][4] = {};

    for (int k0 = 0; k0 < K; k0 += 16) {
        float4 av = *(const float4*)&A[(r0 + ai) * K + k0 + ak];
        As[ak + 0][ai] = av.x;
        As[ak + 1][ai] = av.y;
        As[ak + 2][ai] = av.z;
        As[ak + 3][ai] = av.w;
        *(float4*)&Bs[bk][bj] = *(const float4*)&B[(k0 + bk) * N + c0 + bj];
        __syncthreads();
#pragma unroll
        for (int kk = 0; kk < 16; kk++) {
            float4 a = *(const float4*)&As[kk][ty << 2];
            float4 b = *(const float4*)&Bs[kk][tx << 2];
            float ar[4] = {a.x, a.y, a.z, a.w};
            float br[4] = {b.x, b.y, b.z, b.w};
#pragma unroll
            for (int i = 0; i < 4; i++)
#pragma unroll
                for (int j = 0; j < 4; j++) acc[i][j] += ar[i] * br[j];
        }
        __syncthreads();
    }

#pragma unroll
    for (int i = 0; i < 4; i++) {
        int row = r0 + (ty << 2) + i;
#pragma unroll
        for (int j = 0; j < 4; j++) {
            int col = c0 + (tx << 2) + j;
            float vv = acc[i][j] + bias[col];
            if (ACT == 1) vv = 0.5f * vv * (1.0f + erff(vv * 0.70710678118654752f));
            C[row * N + col] = vv;
        }
    }
}

// ---------------------------------------------------------------------------
// Causal attention, flash-style online softmax.
// Block = (qtile, head, batch); 64 query rows per block; 256 threads.
// Thread (i = t/4, g = t%4): handles row i, 16-wide j/d slice g*16..g*16+15.
// smem: Qs[64][65], Ks[64][65] (reused for P), Vs[64][65] = 49920 B dynamic.
// ---------------------------------------------------------------------------
__global__ void attn_kernel(const float* __restrict__ q, const float* __restrict__ k,
                            const float* __restrict__ v, float* __restrict__ o) {
    extern __shared__ float sm[];
    float* Qs = sm;              // [64][65]
    float* Ks = sm + 64 * 65;    // [64][65], reused as P
    float* Vs = Ks + 64 * 65;    // [64][65]

    int qt = blockIdx.x, h = blockIdx.y, b = blockIdx.z;
    int t = threadIdx.x;
    int i = t >> 2, g = t & 3;
    int rowbase = b * CS;
    int colbase = h * CHD;

    // Load Q tile, pre-scaled by 1/sqrt(dk)
    for (int idx = t; idx < 64 * 64; idx += 256) {
        int r = idx >> 6, d = idx & 63;
        Qs[r * 65 + d] = q[(rowbase + qt * 64 + r) * CD + colbase + d] * 0.125f;
    }

    float m = -1e30f, l = 0.0f;
    float acc[16];
#pragma unroll
    for (int dd = 0; dd < 16; dd++) acc[dd] = 0.0f;

    for (int kt = 0; kt <= qt; kt++) {
        __syncthreads();  // prior PV reads done before overwriting Ks/Vs
        for (int idx = t; idx < 64 * 64; idx += 256) {
            int r = idx >> 6, d = idx & 63;
            int grow = (rowbase + kt * 64 + r) * CD + colbase + d;
            Ks[r * 65 + d] = k[grow];
            Vs[r * 65 + d] = v[grow];
        }
        __syncthreads();

        // Scores for this thread's 16 j's
        float s[16];
#pragma unroll
        for (int jj = 0; jj < 16; jj++) {
            int j = (g << 4) + jj;
            float a = 0.0f;
#pragma unroll
            for (int d = 0; d < 64; d++) a += Qs[i * 65 + d] * Ks[j * 65 + d];
            s[jj] = a;
        }
        if (kt == qt) {
#pragma unroll
            for (int jj = 0; jj < 16; jj++)
                if ((g << 4) + jj > i) s[jj] = -1e9f;
        }

        // Row max across the 4 threads of row i (consecutive lanes)
        float tm = s[0];
#pragma unroll
        for (int jj = 1; jj < 16; jj++) tm = fmaxf(tm, s[jj]);
        tm = fmaxf(tm, __shfl_xor_sync(0xffffffffu, tm, 1));
        tm = fmaxf(tm, __shfl_xor_sync(0xffffffffu, tm, 2));

        float mn = fmaxf(m, tm);
        float alpha = __expf(m - mn);
        float ls = 0.0f;
#pragma unroll
        for (int jj = 0; jj < 16; jj++) {
            float p = __expf(s[jj] - mn);
            s[jj] = p;
            ls += p;
        }
        ls += __shfl_xor_sync(0xffffffffu, ls, 1);
        ls += __shfl_xor_sync(0xffffffffu, ls, 2);
        l = l * alpha + ls;
        m = mn;
#pragma unroll
        for (int dd = 0; dd < 16; dd++) acc[dd] *= alpha;

        __syncthreads();  // everyone done reading Ks -> safe to overwrite with P
#pragma unroll
        for (int jj = 0; jj < 16; jj++) Ks[i * 65 + (g << 4) + jj] = s[jj];
        __syncwarp();     // P producers/consumers of a row share the warp

        // acc += P @ V for this thread's 16 d's
#pragma unroll
        for (int j = 0; j < 64; j++) {
            float p = Ks[i * 65 + j];
#pragma unroll
            for (int dd = 0; dd < 16; dd++) acc[dd] += p * Vs[j * 65 + (g << 4) + dd];
        }
    }

    float inv = 1.0f / l;
    int orow = (rowbase + qt * 64 + i) * CD + colbase + (g << 4);
#pragma unroll
    for (int dd = 0; dd < 16; dd++) o[orow + dd] = acc[dd] * inv;
}

// ---------------------------------------------------------------------------
// LayerNorm over D=768, optional residual add: out = LN(x + res)
// One block per row, 256 threads, 3 elements per thread.
// ---------------------------------------------------------------------------
__global__ void ln_kernel(const float* __restrict__ x, const float* __restrict__ res,
                          const float* __restrict__ g, const float* __restrict__ b,
                          float* __restrict__ out) {
    int r = blockIdx.x, t = threadIdx.x;
    __shared__ float red[8];
    int base = r * CD;
    float a0 = x[base + t], a1 = x[base + t + 256], a2 = x[base + t + 512];
    if (res) {
        a0 += res[base + t];
        a1 += res[base + t + 256];
        a2 += res[base + t + 512];
    }
    float sm = a0 + a1 + a2;
#pragma unroll
    for (int o = 16; o; o >>= 1) sm += __shfl_xor_sync(0xffffffffu, sm, o);
    if ((t & 31) == 0) red[t >> 5] = sm;
    __syncthreads();
    float mean = (red[0] + red[1] + red[2] + red[3] + red[4] + red[5] + red[6] + red[7]) *
                 (1.0f / CD);
    __syncthreads();
    float d0 = a0 - mean, d1 = a1 - mean, d2 = a2 - mean;
    float vs = d0 * d0 + d1 * d1 + d2 * d2;
#pragma unroll
    for (int o = 16; o; o >>= 1) vs += __shfl_xor_sync(0xffffffffu, vs, o);
    if ((t & 31) == 0) red[t >> 5] = vs;
    __syncthreads();
    float var = (red[0] + red[1] + red[2] + red[3] + red[4] + red[5] + red[6] + red[7]) *
                (1.0f / CD);
    float rstd = rsqrtf(var + 1e-5f);
    out[base + t]       = d0 * rstd * g[t]       + b[t];
    out[base + t + 256] = d1 * rstd * g[t + 256] + b[t + 256];
    out[base + t + 512] = d2 * rstd * g[t + 512] + b[t + 512];
}

// ---------------------------------------------------------------------------
// Launch
// ---------------------------------------------------------------------------
extern "C" void kernel_launch(void* const* d_in, const int* in_sizes, int n_in,
                              void* d_out, int out_size) {
    const int*   ids   = (const int*)  d_in[0];
    const float* emb   = (const float*)d_in[1];
    const float* pe    = (const float*)d_in[2];
    const float* wq    = (const float*)d_in[3];
    const float* bq    = (const float*)d_in[4];
    const float* wk    = (const float*)d_in[5];
    const float* bk    = (const float*)d_in[6];
    const float* wv    = (const float*)d_in[7];
    const float* bv    = (const float*)d_in[8];
    const float* wo    = (const float*)d_in[9];
    const float* bo    = (const float*)d_in[10];
    const float* ln1g  = (const float*)d_in[11];
    const float* ln1b  = (const float*)d_in[12];
    const float* w1    = (const float*)d_in[13];
    const float* b1    = (const float*)d_in[14];
    const float* w2    = (const float*)d_in[15];
    const float* b2    = (const float*)d_in[16];
    const float* ln2g  = (const float*)d_in[17];
    const float* ln2b  = (const float*)d_in[18];
    const float* lnfg  = (const float*)d_in[19];
    const float* lnfb  = (const float*)d_in[20];
    const float* headw = (const float*)d_in[21];
    const float* headb = (const float*)d_in[22];
    float* out = (float*)d_out;

    float *x, *q, *k, *v, *att, *ff;
    cudaGetSymbolAddress((void**)&x,   g_x);
    cudaGetSymbolAddress((void**)&q,   g_q);
    cudaGetSymbolAddress((void**)&k,   g_k);
    cudaGetSymbolAddress((void**)&v,   g_v);
    cudaGetSymbolAddress((void**)&att, g_att);
    cudaGetSymbolAddress((void**)&ff,  g_ff);

    const int SMEM_ATTN = 3 * 64 * 65 * (int)sizeof(float);  // 49920 B
    cudaFuncSetAttribute(attn_kernel, cudaFuncAttributeMaxDynamicSharedMemorySize, SMEM_ATTN);

    embed_kernel<<<(CM * CD + 255) / 256, 256>>>(ids, emb, pe, x);

    dim3 gP (CD / 64, CM / 64);   // proj GEMMs:  2048 x 768
    dim3 gF1(CF / 64, CM / 64);   // ffn1:        2048 x 3072
    dim3 gH (CV / 64, CM / 64);   // head:        2048 x 32000

    for (int l = 0; l < CL; l++) {
        size_t wOff = (size_t)l * CD * CD;
        gemm_kernel<0><<<gP, 256>>>(x, wq + wOff, bq + l * CD, q, CM, CD, CD);
        gemm_kernel<0><<<gP, 256>>>(x, wk + wOff, bk + l * CD, k, CM, CD, CD);
        gemm_kernel<0><<<gP, 256>>>(x, wv + wOff, bv + l * CD, v, CM, CD, CD);
        attn_kernel<<<dim3(CS / 64, CH, CB), 256, SMEM_ATTN>>>(q, k, v, att);
        gemm_kernel<0><<<gP, 256>>>(att, wo + wOff, bo + l * CD, q, CM, CD, CD);
        ln_kernel<<<CM, 256>>>(x, q, ln1g + l * CD, ln1b + l * CD, x);
        gemm_kernel<1><<<gF1, 256>>>(x, w1 + (size_t)l * CD * CF, b1 + l * CF, ff, CM, CF, CD);
        gemm_kernel<0><<<gP, 256>>>(ff, w2 + (size_t)l * CF * CD, b2 + l * CD, q, CM, CD, CF);
        ln_kernel<<<CM, 256>>>(x, q, ln2g + l * CD, ln2b + l * CD, x);
    }

    ln_kernel<<<CM, 256>>>(x, nullptr, lnfg, lnfb, q);
    gemm_kernel<0><<<gH, 256>>>(q, headw, headb, out, CM, CV, CD);
}

// round 4
// speedup vs baseline: 1.3052x; 1.3052x over previous
#include <cuda_runtime.h>
#include <math.h>
#include <stdint.h>

// Model constants
constexpr int CD  = 768;
constexpr int CS  = 1024;
constexpr int CB  = 2;
constexpr int CM  = CB * CS;  // 2048
constexpr int CH  = 12;
constexpr int CHD = 64;
constexpr int CL  = 6;
constexpr int CF  = 3072;
constexpr int CV  = 32000;

// Scratch
__device__ float g_x  [CM * CD];
__device__ float g_q  [CM * CD];
__device__ float g_k  [CM * CD];
__device__ float g_v  [CM * CD];
__device__ float g_att[CM * CD];
__device__ float g_ff [CM * CF];

// ---------------------------------------------------------------------------
// Helpers
// ---------------------------------------------------------------------------
__device__ __forceinline__ uint32_t f2tf(float f) {
    uint32_t u;
    asm("cvt.rna.tf32.f32 %0, %1;" : "=r"(u) : "f"(f));
    return u;
}
__device__ __forceinline__ void mma_tf32(float* c, const uint32_t* a, const uint32_t* b) {
    asm volatile(
        "mma.sync.aligned.m16n8k8.row.col.f32.tf32.tf32.f32 "
        "{%0,%1,%2,%3}, {%4,%5,%6,%7}, {%8,%9}, {%0,%1,%2,%3};"
        : "+f"(c[0]), "+f"(c[1]), "+f"(c[2]), "+f"(c[3])
        : "r"(a[0]), "r"(a[1]), "r"(a[2]), "r"(a[3]), "r"(b[0]), "r"(b[1]));
}

// ---------------------------------------------------------------------------
// Embedding
// ---------------------------------------------------------------------------
__global__ void embed_kernel(const int* __restrict__ ids, const float* __restrict__ emb,
                             const float* __restrict__ pe, float* __restrict__ out) {
    int idx = blockIdx.x * blockDim.x + threadIdx.x;
    if (idx >= CM * CD) return;
    int r = idx / CD;
    int d = idx - r * CD;
    int s = r & (CS - 1);
    out[idx] = emb[ids[r] * CD + d] * 27.712812921102035f + pe[s * CD + d];
}

// ---------------------------------------------------------------------------
// tf32 mma.sync GEMM: C[M,N] = A[M,K] @ B[K,N] + bias  (ACT=1 -> exact GELU)
// CTA 128x128, BK=32, 256 threads (8 warps as 2x4), warp tile 64x32.
// SMEM: [k][col] with pad 136 and XOR swizzle col ^ (((k>>2)&7)<<2).
// grid = (M/128, N/128); x over M so co-resident CTAs share B tiles in L2.
// ---------------------------------------------------------------------------
template <int ACT>
__global__ void __launch_bounds__(256, 2) gemm_mma(const float* __restrict__ A,
                                                   const float* __restrict__ B,
                                                   const float* __restrict__ bias,
                                                   float* __restrict__ C, int N, int K) {
    __shared__ uint32_t As[32][136];
    __shared__ uint32_t Bs[32][136];

    const int tid  = threadIdx.x;
    const int lane = tid & 31;
    const int wid  = tid >> 5;
    const int wr   = wid >> 2;   // 0..1
    const int wc   = wid & 3;    // 0..3
    const int lr   = lane >> 2;  // 0..7
    const int lc   = lane & 3;   // 0..3
    const int r0   = blockIdx.x * 128;
    const int c0   = blockIdx.y * 128;
    const int NK   = K >> 5;

    // Staging thread assignments (per it in 0..3, i = tid + it*256)
    int am[4], ak[4], bk[4], bn[4];
#pragma unroll
    for (int it = 0; it < 4; it++) {
        int i = tid + it * 256;
        am[it] = i >> 3;          // 0..127
        ak[it] = (i & 7) << 2;    // 0,4,..,28
        bk[it] = i >> 5;          // 0..31
        bn[it] = (i & 31) << 2;   // 0,4,..,124
    }

    const float* Ag = A + (size_t)r0 * K;
    const float* Bg = B + c0;

    float cc[4][4][4];
#pragma unroll
    for (int mt = 0; mt < 4; mt++)
#pragma unroll
        for (int nt = 0; nt < 4; nt++)
#pragma unroll
            for (int j = 0; j < 4; j++) cc[mt][nt][j] = 0.0f;

    float4 pa[4], pb[4];
#pragma unroll
    for (int it = 0; it < 4; it++) {
        pa[it] = *(const float4*)(Ag + (size_t)am[it] * K + ak[it]);
        pb[it] = *(const float4*)(Bg + (size_t)bk[it] * N + bn[it]);
    }

    for (int kc = 0; kc < NK; kc++) {
        __syncthreads();
        // Store staged chunk (convert to tf32, swizzled)
#pragma unroll
        for (int it = 0; it < 4; it++) {
            int xa = ak[it];                   // ((ak/4)&7)*4 == ak (ak<32)
            int mcol = am[it] ^ xa;
            As[ak[it] + 0][mcol] = f2tf(pa[it].x);
            As[ak[it] + 1][mcol] = f2tf(pa[it].y);
            As[ak[it] + 2][mcol] = f2tf(pa[it].z);
            As[ak[it] + 3][mcol] = f2tf(pa[it].w);
            int xb = ((bk[it] >> 2) & 7) << 2;
            uint4 bv;
            bv.x = f2tf(pb[it].x);
            bv.y = f2tf(pb[it].y);
            bv.z = f2tf(pb[it].z);
            bv.w = f2tf(pb[it].w);
            *(uint4*)&Bs[bk[it]][bn[it] ^ xb] = bv;
        }
        __syncthreads();

        // Prefetch next chunk
        if (kc + 1 < NK) {
#pragma unroll
            for (int it = 0; it < 4; it++) {
                pa[it] = *(const float4*)(Ag + (size_t)am[it] * K + (kc + 1) * 32 + ak[it]);
                pb[it] = *(const float4*)(Bg + (size_t)((kc + 1) * 32 + bk[it]) * N + bn[it]);
            }
        }

        // Compute 4 k-steps of 8
#pragma unroll
        for (int ks = 0; ks < 4; ks++) {
            const int x0 = ((2 * ks) & 7) << 2;
            const int x1 = ((2 * ks + 1) & 7) << 2;
            const int k0 = ks * 8 + lc;
            uint32_t af[4][4], bf[4][2];
#pragma unroll
            for (int mt = 0; mt < 4; mt++) {
                int m = wr * 64 + mt * 16 + lr;
                af[mt][0] = As[k0][m ^ x0];
                af[mt][1] = As[k0][(m + 8) ^ x0];
                af[mt][2] = As[k0 + 4][m ^ x1];
                af[mt][3] = As[k0 + 4][(m + 8) ^ x1];
            }
#pragma unroll
            for (int nt = 0; nt < 4; nt++) {
                int n = wc * 32 + nt * 8 + lr;
                bf[nt][0] = Bs[k0][n ^ x0];
                bf[nt][1] = Bs[k0 + 4][n ^ x1];
            }
#pragma unroll
            for (int mt = 0; mt < 4; mt++)
#pragma unroll
                for (int nt = 0; nt < 4; nt++) mma_tf32(cc[mt][nt], af[mt], bf[nt]);
        }
    }

    // Epilogue: bias (+GELU), direct float2 stores
#pragma unroll
    for (int nt = 0; nt < 4; nt++) {
        int col = c0 + wc * 32 + nt * 8 + 2 * lc;
        float b0 = bias[col], b1 = bias[col + 1];
#pragma unroll
        for (int mt = 0; mt < 4; mt++) {
            int rlo = r0 + wr * 64 + mt * 16 + lr;
            float o0 = cc[mt][nt][0] + b0;
            float o1 = cc[mt][nt][1] + b1;
            float o2 = cc[mt][nt][2] + b0;
            float o3 = cc[mt][nt][3] + b1;
            if (ACT == 1) {
                o0 = 0.5f * o0 * (1.0f + erff(o0 * 0.70710678118654752f));
                o1 = 0.5f * o1 * (1.0f + erff(o1 * 0.70710678118654752f));
                o2 = 0.5f * o2 * (1.0f + erff(o2 * 0.70710678118654752f));
                o3 = 0.5f * o3 * (1.0f + erff(o3 * 0.70710678118654752f));
            }
            float2 vlo = make_float2(o0, o1);
            float2 vhi = make_float2(o2, o3);
            *(float2*)&C[(size_t)rlo * N + col]       = vlo;
            *(float2*)&C[(size_t)(rlo + 8) * N + col] = vhi;
        }
    }
}

// ---------------------------------------------------------------------------
// Causal attention (fp32, unchanged)
// ---------------------------------------------------------------------------
__global__ void attn_kernel(const float* __restrict__ q, const float* __restrict__ k,
                            const float* __restrict__ v, float* __restrict__ o) {
    extern __shared__ float sm[];
    float* Qs = sm;
    float* Ks = sm + 64 * 65;
    float* Vs = Ks + 64 * 65;

    int qt = blockIdx.x, h = blockIdx.y, b = blockIdx.z;
    int t = threadIdx.x;
    int i = t >> 2, g = t & 3;
    int rowbase = b * CS;
    int colbase = h * CHD;

    for (int idx = t; idx < 64 * 64; idx += 256) {
        int r = idx >> 6, d = idx & 63;
        Qs[r * 65 + d] = q[(rowbase + qt * 64 + r) * CD + colbase + d] * 0.125f;
    }

    float m = -1e30f, l = 0.0f;
    float acc[16];
#pragma unroll
    for (int dd = 0; dd < 16; dd++) acc[dd] = 0.0f;

    for (int kt = 0; kt <= qt; kt++) {
        __syncthreads();
        for (int idx = t; idx < 64 * 64; idx += 256) {
            int r = idx >> 6, d = idx & 63;
            int grow = (rowbase + kt * 64 + r) * CD + colbase + d;
            Ks[r * 65 + d] = k[grow];
            Vs[r * 65 + d] = v[grow];
        }
        __syncthreads();

        float s[16];
#pragma unroll
        for (int jj = 0; jj < 16; jj++) {
            int j = (g << 4) + jj;
            float a = 0.0f;
#pragma unroll
            for (int d = 0; d < 64; d++) a += Qs[i * 65 + d] * Ks[j * 65 + d];
            s[jj] = a;
        }
        if (kt == qt) {
#pragma unroll
            for (int jj = 0; jj < 16; jj++)
                if ((g << 4) + jj > i) s[jj] = -1e9f;
        }

        float tm = s[0];
#pragma unroll
        for (int jj = 1; jj < 16; jj++) tm = fmaxf(tm, s[jj]);
        tm = fmaxf(tm, __shfl_xor_sync(0xffffffffu, tm, 1));
        tm = fmaxf(tm, __shfl_xor_sync(0xffffffffu, tm, 2));

        float mn = fmaxf(m, tm);
        float alpha = __expf(m - mn);
        float ls = 0.0f;
#pragma unroll
        for (int jj = 0; jj < 16; jj++) {
            float p = __expf(s[jj] - mn);
            s[jj] = p;
            ls += p;
        }
        ls += __shfl_xor_sync(0xffffffffu, ls, 1);
        ls += __shfl_xor_sync(0xffffffffu, ls, 2);
        l = l * alpha + ls;
        m = mn;
#pragma unroll
        for (int dd = 0; dd < 16; dd++) acc[dd] *= alpha;

        __syncthreads();
#pragma unroll
        for (int jj = 0; jj < 16; jj++) Ks[i * 65 + (g << 4) + jj] = s[jj];
        __syncwarp();

#pragma unroll
        for (int j = 0; j < 64; j++) {
            float p = Ks[i * 65 + j];
#pragma unroll
            for (int dd = 0; dd < 16; dd++) acc[dd] += p * Vs[j * 65 + (g << 4) + dd];
        }
    }

    float inv = 1.0f / l;
    int orow = (rowbase + qt * 64 + i) * CD + colbase + (g << 4);
#pragma unroll
    for (int dd = 0; dd < 16; dd++) o[orow + dd] = acc[dd] * inv;
}

// ---------------------------------------------------------------------------
// LayerNorm (unchanged)
// ---------------------------------------------------------------------------
__global__ void ln_kernel(const float* __restrict__ x, const float* __restrict__ res,
                          const float* __restrict__ g, const float* __restrict__ b,
                          float* __restrict__ out) {
    int r = blockIdx.x, t = threadIdx.x;
    __shared__ float red[8];
    int base = r * CD;
    float a0 = x[base + t], a1 = x[base + t + 256], a2 = x[base + t + 512];
    if (res) {
        a0 += res[base + t];
        a1 += res[base + t + 256];
        a2 += res[base + t + 512];
    }
    float sm = a0 + a1 + a2;
#pragma unroll
    for (int o = 16; o; o >>= 1) sm += __shfl_xor_sync(0xffffffffu, sm, o);
    if ((t & 31) == 0) red[t >> 5] = sm;
    __syncthreads();
    float mean = (red[0] + red[1] + red[2] + red[3] + red[4] + red[5] + red[6] + red[7]) *
                 (1.0f / CD);
    __syncthreads();
    float d0 = a0 - mean, d1 = a1 - mean, d2 = a2 - mean;
    float vs = d0 * d0 + d1 * d1 + d2 * d2;
#pragma unroll
    for (int o = 16; o; o >>= 1) vs += __shfl_xor_sync(0xffffffffu, vs, o);
    if ((t & 31) == 0) red[t >> 5] = vs;
    __syncthreads();
    float var = (red[0] + red[1] + red[2] + red[3] + red[4] + red[5] + red[6] + red[7]) *
                (1.0f / CD);
    float rstd = rsqrtf(var + 1e-5f);
    out[base + t]       = d0 * rstd * g[t]       + b[t];
    out[base + t + 256] = d1 * rstd * g[t + 256] + b[t + 256];
    out[base + t + 512] = d2 * rstd * g[t + 512] + b[t + 512];
}

// ---------------------------------------------------------------------------
// Launch
// ---------------------------------------------------------------------------
extern "C" void kernel_launch(void* const* d_in, const int* in_sizes, int n_in,
                              void* d_out, int out_size) {
    const int*   ids   = (const int*)  d_in[0];
    const float* emb   = (const float*)d_in[1];
    const float* pe    = (const float*)d_in[2];
    const float* wq    = (const float*)d_in[3];
    const float* bq    = (const float*)d_in[4];
    const float* wk    = (const float*)d_in[5];
    const float* bk    = (const float*)d_in[6];
    const float* wv    = (const float*)d_in[7];
    const float* bv    = (const float*)d_in[8];
    const float* wo    = (const float*)d_in[9];
    const float* bo    = (const float*)d_in[10];
    const float* ln1g  = (const float*)d_in[11];
    const float* ln1b  = (const float*)d_in[12];
    const float* w1    = (const float*)d_in[13];
    const float* b1    = (const float*)d_in[14];
    const float* w2    = (const float*)d_in[15];
    const float* b2    = (const float*)d_in[16];
    const float* ln2g  = (const float*)d_in[17];
    const float* ln2b  = (const float*)d_in[18];
    const float* lnfg  = (const float*)d_in[19];
    const float* lnfb  = (const float*)d_in[20];
    const float* headw = (const float*)d_in[21];
    const float* headb = (const float*)d_in[22];
    float* out = (float*)d_out;

    float *x, *q, *k, *v, *att, *ff;
    cudaGetSymbolAddress((void**)&x,   g_x);
    cudaGetSymbolAddress((void**)&q,   g_q);
    cudaGetSymbolAddress((void**)&k,   g_k);
    cudaGetSymbolAddress((void**)&v,   g_v);
    cudaGetSymbolAddress((void**)&att, g_att);
    cudaGetSymbolAddress((void**)&ff,  g_ff);

    const int SMEM_ATTN = 3 * 64 * 65 * (int)sizeof(float);
    cudaFuncSetAttribute(attn_kernel, cudaFuncAttributeMaxDynamicSharedMemorySize, SMEM_ATTN);

    embed_kernel<<<(CM * CD + 255) / 256, 256>>>(ids, emb, pe, x);

    dim3 gP (CM / 128, CD / 128);   // 16 x 6
    dim3 gF1(CM / 128, CF / 128);   // 16 x 24
    dim3 gH (CM / 128, CV / 128);   // 16 x 250

    for (int l = 0; l < CL; l++) {
        size_t wOff = (size_t)l * CD * CD;
        gemm_mma<0><<<gP, 256>>>(x, wq + wOff, bq + l * CD, q, CD, CD);
        gemm_mma<0><<<gP, 256>>>(x, wk + wOff, bk + l * CD, k, CD, CD);
        gemm_mma<0><<<gP, 256>>>(x, wv + wOff, bv + l * CD, v, CD, CD);
        attn_kernel<<<dim3(CS / 64, CH, CB), 256, SMEM_ATTN>>>(q, k, v, att);
        gemm_mma<0><<<gP, 256>>>(att, wo + wOff, bo + l * CD, q, CD, CD);
        ln_kernel<<<CM, 256>>>(x, q, ln1g + l * CD, ln1b + l * CD, x);
        gemm_mma<1><<<gF1, 256>>>(x, w1 + (size_t)l * CD * CF, b1 + l * CF, ff, CF, CD);
        gemm_mma<0><<<gP, 256>>>(ff, w2 + (size_t)l * CF * CD, b2 + l * CD, q, CD, CF);
        ln_kernel<<<CM, 256>>>(x, q, ln2g + l * CD, ln2b + l * CD, x);
    }

    ln_kernel<<<CM, 256>>>(x, nullptr, lnfg, lnfb, q);
    gemm_mma<0><<<gH, 256>>>(q, headw, headb, out, CV, CD);
}

// round 7
// speedup vs baseline: 1.8171x; 1.3922x over previous
#include <cuda_runtime.h>
#include <math.h>
#include <stdint.h>

// Model constants
constexpr int CD  = 768;
constexpr int CS  = 1024;
constexpr int CB  = 2;
constexpr int CM  = CB * CS;  // 2048
constexpr int CH  = 12;
constexpr int CHD = 64;
constexpr int CL  = 6;
constexpr int CF  = 3072;
constexpr int CV  = 32000;

// Scratch
__device__ float g_x  [CM * CD];
__device__ float g_q  [CM * CD];
__device__ float g_k  [CM * CD];
__device__ float g_v  [CM * CD];
__device__ float g_att[CM * CD];
__device__ float g_ff [CM * CF];

// Pre-converted (tf32-rounded) weights
constexpr size_t PW   = (size_t)CL * CD * CD;
constexpr size_t PF   = (size_t)CL * CD * CF;
constexpr size_t OQ   = 0;
constexpr size_t OKw  = PW;
constexpr size_t OVw  = 2 * PW;
constexpr size_t OOw  = 3 * PW;
constexpr size_t O1w  = 4 * PW;
constexpr size_t O2w  = 4 * PW + PF;
constexpr size_t OHw  = 4 * PW + 2 * PF;
constexpr size_t WTOT = 4 * PW + 2 * PF + (size_t)CD * CV;
__device__ float g_w[WTOT];

// Single extern shared symbol, cast per-kernel
extern __shared__ char s_raw[];

// ---------------------------------------------------------------------------
// Helpers
// ---------------------------------------------------------------------------
__device__ __forceinline__ uint32_t f2tf(float f) {
    uint32_t u;
    asm("cvt.rna.tf32.f32 %0, %1;" : "=r"(u) : "f"(f));
    return u;
}
__device__ __forceinline__ void mma_tf32(float* c, const uint32_t* a, const uint32_t* b) {
    asm volatile(
        "mma.sync.aligned.m16n8k8.row.col.f32.tf32.tf32.f32 "
        "{%0,%1,%2,%3}, {%4,%5,%6,%7}, {%8,%9}, {%0,%1,%2,%3};"
        : "+f"(c[0]), "+f"(c[1]), "+f"(c[2]), "+f"(c[3])
        : "r"(a[0]), "r"(a[1]), "r"(a[2]), "r"(a[3]), "r"(b[0]), "r"(b[1]));
}
#define CP_ASYNC16(dst, src) \
    asm volatile("cp.async.ca.shared.global [%0], [%1], 16;" :: "r"(dst), "l"(src))
#define CP_COMMIT() asm volatile("cp.async.commit_group;")
#define CP_WAIT1()  asm volatile("cp.async.wait_group 1;")

// ---------------------------------------------------------------------------
// Weight conversion (fp32 -> tf32-rounded fp32), float4 grid-stride
// ---------------------------------------------------------------------------
__global__ void cvt_kernel(const float* __restrict__ src, float* __restrict__ dst, int n4) {
    int i = blockIdx.x * blockDim.x + threadIdx.x;
    int stride = gridDim.x * blockDim.x;
    for (; i < n4; i += stride) {
        float4 v = *(const float4*)(src + (size_t)i * 4);
        uint4 u;
        u.x = f2tf(v.x);
        u.y = f2tf(v.y);
        u.z = f2tf(v.z);
        u.w = f2tf(v.w);
        *(uint4*)(dst + (size_t)i * 4) = u;
    }
}

// ---------------------------------------------------------------------------
// Embedding
// ---------------------------------------------------------------------------
__global__ void embed_kernel(const int* __restrict__ ids, const float* __restrict__ emb,
                             const float* __restrict__ pe, float* __restrict__ out) {
    int idx = blockIdx.x * blockDim.x + threadIdx.x;
    if (idx >= CM * CD) return;
    int r = idx / CD;
    int d = idx - r * CD;
    int s = r & (CS - 1);
    out[idx] = emb[ids[r] * CD + d] * 27.712812921102035f + pe[s * CD + d];
}

// ---------------------------------------------------------------------------
// tf32 mma.sync GEMM core: C[M,N] = A[M,K] @ B[K,N] + bias (ACT=1: exact GELU)
// BM x 128 CTA tile, BK=16, 3-stage cp.async pipeline for B (pre-converted),
// register-staged A with cvt. 256 threads = 8 warps (2 x 4), warp BM/2 x 32.
// SMEM: A [m][20] pad layout; B [k][n ^ ((k&3)<<3)] XOR swizzle.
// ---------------------------------------------------------------------------
template <int ACT, int BM>
__device__ __forceinline__ void gemm_core(const float* __restrict__ A,
                                          const float* __restrict__ B,
                                          const float* __restrict__ bias,
                                          float* __restrict__ C,
                                          int N, int K, int r0, int c0,
                                          uint32_t* sm) {
    constexpr int AW  = 20;
    constexpr int SA  = BM * AW;      // A stage words
    constexpr int SB  = 16 * 128;     // B stage words
    constexpr int ABo = 3 * SA;       // B region word offset
    constexpr int AIT = BM / 64;      // A float4s per thread per stage
    constexpr int MT  = BM / 32;      // 16-row m-tiles per warp

    const int tid  = threadIdx.x;
    const int lane = tid & 31;
    const int wid  = tid >> 5;
    const int wr   = wid >> 2;
    const int wc   = wid & 3;
    const int lr   = lane >> 2;
    const int lc   = lane & 3;
    const int NK   = K >> 4;

    const float* Ag = A + (size_t)r0 * K;
    const float* Bg = B + c0;
    const uint32_t smb = (uint32_t)__cvta_generic_to_shared(sm);

    float cc[MT][4][4];
#pragma unroll
    for (int mt = 0; mt < MT; mt++)
#pragma unroll
        for (int nt = 0; nt < 4; nt++)
#pragma unroll
            for (int j = 0; j < 4; j++) cc[mt][nt][j] = 0.0f;

    int am[AIT], ak[AIT];
#pragma unroll
    for (int it = 0; it < AIT; it++) {
        int i = tid + it * 256;
        am[it] = i >> 2;
        ak[it] = (i & 3) << 2;
    }

    float4 rA[2][AIT];

    // ---- prologue: LDG A stages 0,1; cp.async B stages 0,1; STS A stage 0
#pragma unroll
    for (int s = 0; s < 2; s++)
#pragma unroll
        for (int it = 0; it < AIT; it++)
            rA[s][it] = *(const float4*)(Ag + (size_t)am[it] * K + s * 16 + ak[it]);

#pragma unroll
    for (int s = 0; s < 2; s++) {
#pragma unroll
        for (int g2 = 0; g2 < 2; g2++) {
            int g = tid + g2 * 256;
            int k = g >> 5, n4 = (g & 31) << 2;
            uint32_t dst = smb + 4u * (ABo + s * SB + k * 128 + (n4 ^ ((k & 3) << 3)));
            CP_ASYNC16(dst, Bg + (size_t)(s * 16 + k) * N + n4);
        }
        CP_COMMIT();
    }
#pragma unroll
    for (int it = 0; it < AIT; it++) {
        uint4 v;
        v.x = f2tf(rA[0][it].x);
        v.y = f2tf(rA[0][it].y);
        v.z = f2tf(rA[0][it].z);
        v.w = f2tf(rA[0][it].w);
        *(uint4*)&sm[am[it] * AW + ak[it]] = v;
    }

    // ---- main loop
#pragma unroll 1
    for (int j = 0; j < NK; j++) {
        CP_WAIT1();
        __syncthreads();

        if (j + 2 < NK) {
#pragma unroll
            for (int g2 = 0; g2 < 2; g2++) {
                int g = tid + g2 * 256;
                int k = g >> 5, n4 = (g & 31) << 2;
                uint32_t dst = smb + 4u * (ABo + ((j + 2) % 3) * SB + k * 128 +
                                           (n4 ^ ((k & 3) << 3)));
                CP_ASYNC16(dst, Bg + (size_t)((j + 2) * 16 + k) * N + n4);
            }
        }
        CP_COMMIT();

        if (j + 1 < NK) {
            uint32_t* As1 = sm + ((j + 1) % 3) * SA;
#pragma unroll
            for (int it = 0; it < AIT; it++) {
                uint4 v;
                v.x = f2tf(rA[(j + 1) & 1][it].x);
                v.y = f2tf(rA[(j + 1) & 1][it].y);
                v.z = f2tf(rA[(j + 1) & 1][it].z);
                v.w = f2tf(rA[(j + 1) & 1][it].w);
                *(uint4*)&As1[am[it] * AW + ak[it]] = v;
            }
        }
        if (j + 2 < NK) {
#pragma unroll
            for (int it = 0; it < AIT; it++)
                rA[j & 1][it] = *(const float4*)(Ag + (size_t)am[it] * K + (j + 2) * 16 + ak[it]);
        }

        const uint32_t* As_ = sm + (j % 3) * SA;
        const uint32_t* Bs_ = sm + ABo + (j % 3) * SB;
#pragma unroll
        for (int ks = 0; ks < 2; ks++) {
            const int k0 = ks * 8 + lc;
            uint32_t af[MT][4], bf[4][2];
#pragma unroll
            for (int mt = 0; mt < MT; mt++) {
                int m = wr * (BM / 2) + mt * 16 + lr;
                af[mt][0] = As_[m * AW + k0];
                af[mt][1] = As_[(m + 8) * AW + k0];
                af[mt][2] = As_[m * AW + k0 + 4];
                af[mt][3] = As_[(m + 8) * AW + k0 + 4];
            }
#pragma unroll
            for (int nt = 0; nt < 4; nt++) {
                int n = wc * 32 + nt * 8 + lr;
                bf[nt][0] = Bs_[k0 * 128 + (n ^ ((k0 & 3) << 3))];
                bf[nt][1] = Bs_[(k0 + 4) * 128 + (n ^ (((k0 + 4) & 3) << 3))];
            }
#pragma unroll
            for (int mt = 0; mt < MT; mt++)
#pragma unroll
                for (int nt = 0; nt < 4; nt++) mma_tf32(cc[mt][nt], af[mt], bf[nt]);
        }
    }

    // ---- epilogue
#pragma unroll
    for (int nt = 0; nt < 4; nt++) {
        int col = c0 + wc * 32 + nt * 8 + 2 * lc;
        float b0 = bias[col], b1 = bias[col + 1];
#pragma unroll
        for (int mt = 0; mt < MT; mt++) {
            int rlo = r0 + wr * (BM / 2) + mt * 16 + lr;
            float o0 = cc[mt][nt][0] + b0;
            float o1 = cc[mt][nt][1] + b1;
            float o2 = cc[mt][nt][2] + b0;
            float o3 = cc[mt][nt][3] + b1;
            if (ACT == 1) {
                o0 = 0.5f * o0 * (1.0f + erff(o0 * 0.70710678118654752f));
                o1 = 0.5f * o1 * (1.0f + erff(o1 * 0.70710678118654752f));
                o2 = 0.5f * o2 * (1.0f + erff(o2 * 0.70710678118654752f));
                o3 = 0.5f * o3 * (1.0f + erff(o3 * 0.70710678118654752f));
            }
            *(float2*)&C[(size_t)rlo * N + col]       = make_float2(o0, o1);
            *(float2*)&C[(size_t)(rlo + 8) * N + col] = make_float2(o2, o3);
        }
    }
}

template <int ACT, int BM>
__global__ void __launch_bounds__(256, 2) gemm_mma(const float* __restrict__ A,
                                                   const float* __restrict__ B,
                                                   const float* __restrict__ bias,
                                                   float* __restrict__ C, int N, int K) {
    gemm_core<ACT, BM>(A, B, bias, C, N, K, blockIdx.x * BM, blockIdx.y * 128,
                       (uint32_t*)s_raw);
}

__global__ void __launch_bounds__(256, 2) gemm_qkv(const float* __restrict__ A,
                                                   const float* __restrict__ Bq,
                                                   const float* __restrict__ Bk,
                                                   const float* __restrict__ Bv,
                                                   const float* __restrict__ bq,
                                                   const float* __restrict__ bk,
                                                   const float* __restrict__ bv,
                                                   float* __restrict__ Cq,
                                                   float* __restrict__ Ck,
                                                   float* __restrict__ Cv) {
    const float* B;
    const float* bi;
    float* C;
    if (blockIdx.z == 0)      { B = Bq; bi = bq; C = Cq; }
    else if (blockIdx.z == 1) { B = Bk; bi = bk; C = Ck; }
    else                      { B = Bv; bi = bv; C = Cv; }
    gemm_core<0, 128>(A, B, bi, C, CD, CD, blockIdx.x * 128, blockIdx.y * 128,
                      (uint32_t*)s_raw);
}

// ---------------------------------------------------------------------------
// Causal attention (fp32)
// ---------------------------------------------------------------------------
__global__ void attn_kernel(const float* __restrict__ q, const float* __restrict__ k,
                            const float* __restrict__ v, float* __restrict__ o) {
    float* sm = (float*)s_raw;
    float* Qs = sm;
    float* Ks = sm + 64 * 65;
    float* Vs = Ks + 64 * 65;

    int qt = blockIdx.x, h = blockIdx.y, b = blockIdx.z;
    int t = threadIdx.x;
    int i = t >> 2, g = t & 3;
    int rowbase = b * CS;
    int colbase = h * CHD;

    for (int idx = t; idx < 64 * 64; idx += 256) {
        int r = idx >> 6, d = idx & 63;
        Qs[r * 65 + d] = q[(rowbase + qt * 64 + r) * CD + colbase + d] * 0.125f;
    }

    float m = -1e30f, l = 0.0f;
    float acc[16];
#pragma unroll
    for (int dd = 0; dd < 16; dd++) acc[dd] = 0.0f;

    for (int kt = 0; kt <= qt; kt++) {
        __syncthreads();
        for (int idx = t; idx < 64 * 64; idx += 256) {
            int r = idx >> 6, d = idx & 63;
            int grow = (rowbase + kt * 64 + r) * CD + colbase + d;
            Ks[r * 65 + d] = k[grow];
            Vs[r * 65 + d] = v[grow];
        }
        __syncthreads();

        float s[16];
#pragma unroll
        for (int jj = 0; jj < 16; jj++) {
            int j = (g << 4) + jj;
            float a = 0.0f;
#pragma unroll
            for (int d = 0; d < 64; d++) a += Qs[i * 65 + d] * Ks[j * 65 + d];
            s[jj] = a;
        }
        if (kt == qt) {
#pragma unroll
            for (int jj = 0; jj < 16; jj++)
                if ((g << 4) + jj > i) s[jj] = -1e9f;
        }

        float tm = s[0];
#pragma unroll
        for (int jj = 1; jj < 16; jj++) tm = fmaxf(tm, s[jj]);
        tm = fmaxf(tm, __shfl_xor_sync(0xffffffffu, tm, 1));
        tm = fmaxf(tm, __shfl_xor_sync(0xffffffffu, tm, 2));

        float mn = fmaxf(m, tm);
        float alpha = __expf(m - mn);
        float ls = 0.0f;
#pragma unroll
        for (int jj = 0; jj < 16; jj++) {
            float p = __expf(s[jj] - mn);
            s[jj] = p;
            ls += p;
        }
        ls += __shfl_xor_sync(0xffffffffu, ls, 1);
        ls += __shfl_xor_sync(0xffffffffu, ls, 2);
        l = l * alpha + ls;
        m = mn;
#pragma unroll
        for (int dd = 0; dd < 16; dd++) acc[dd] *= alpha;

        __syncthreads();
#pragma unroll
        for (int jj = 0; jj < 16; jj++) Ks[i * 65 + (g << 4) + jj] = s[jj];
        __syncwarp();

#pragma unroll
        for (int j = 0; j < 64; j++) {
            float p = Ks[i * 65 + j];
#pragma unroll
            for (int dd = 0; dd < 16; dd++) acc[dd] += p * Vs[j * 65 + (g << 4) + dd];
        }
    }

    float inv = 1.0f / l;
    int orow = (rowbase + qt * 64 + i) * CD + colbase + (g << 4);
#pragma unroll
    for (int dd = 0; dd < 16; dd++) o[orow + dd] = acc[dd] * inv;
}

// ---------------------------------------------------------------------------
// LayerNorm
// ---------------------------------------------------------------------------
__global__ void ln_kernel(const float* __restrict__ x, const float* __restrict__ res,
                          const float* __restrict__ g, const float* __restrict__ b,
                          float* __restrict__ out) {
    int r = blockIdx.x, t = threadIdx.x;
    __shared__ float red[8];
    int base = r * CD;
    float a0 = x[base + t], a1 = x[base + t + 256], a2 = x[base + t + 512];
    if (res) {
        a0 += res[base + t];
        a1 += res[base + t + 256];
        a2 += res[base + t + 512];
    }
    float sm = a0 + a1 + a2;
#pragma unroll
    for (int o = 16; o; o >>= 1) sm += __shfl_xor_sync(0xffffffffu, sm, o);
    if ((t & 31) == 0) red[t >> 5] = sm;
    __syncthreads();
    float mean = (red[0] + red[1] + red[2] + red[3] + red[4] + red[5] + red[6] + red[7]) *
                 (1.0f / CD);
    __syncthreads();
    float d0 = a0 - mean, d1 = a1 - mean, d2 = a2 - mean;
    float vs = d0 * d0 + d1 * d1 + d2 * d2;
#pragma unroll
    for (int o = 16; o; o >>= 1) vs += __shfl_xor_sync(0xffffffffu, vs, o);
    if ((t & 31) == 0) red[t >> 5] = vs;
    __syncthreads();
    float var = (red[0] + red[1] + red[2] + red[3] + red[4] + red[5] + red[6] + red[7]) *
                (1.0f / CD);
    float rstd = rsqrtf(var + 1e-5f);
    out[base + t]       = d0 * rstd * g[t]       + b[t];
    out[base + t + 256] = d1 * rstd * g[t + 256] + b[t + 256];
    out[base + t + 512] = d2 * rstd * g[t + 512] + b[t + 512];
}

// ---------------------------------------------------------------------------
// Launch
// ---------------------------------------------------------------------------
extern "C" void kernel_launch(void* const* d_in, const int* in_sizes, int n_in,
                              void* d_out, int out_size) {
    const int*   ids   = (const int*)  d_in[0];
    const float* emb   = (const float*)d_in[1];
    const float* pe    = (const float*)d_in[2];
    const float* wq    = (const float*)d_in[3];
    const float* bq    = (const float*)d_in[4];
    const float* wk    = (const float*)d_in[5];
    const float* bk    = (const float*)d_in[6];
    const float* wv    = (const float*)d_in[7];
    const float* bv    = (const float*)d_in[8];
    const float* wo    = (const float*)d_in[9];
    const float* bo    = (const float*)d_in[10];
    const float* ln1g  = (const float*)d_in[11];
    const float* ln1b  = (const float*)d_in[12];
    const float* w1    = (const float*)d_in[13];
    const float* b1    = (const float*)d_in[14];
    const float* w2    = (const float*)d_in[15];
    const float* b2    = (const float*)d_in[16];
    const float* ln2g  = (const float*)d_in[17];
    const float* ln2b  = (const float*)d_in[18];
    const float* lnfg  = (const float*)d_in[19];
    const float* lnfb  = (const float*)d_in[20];
    const float* headw = (const float*)d_in[21];
    const float* headb = (const float*)d_in[22];
    float* out = (float*)d_out;

    float *x, *q, *k, *v, *att, *ff, *w;
    cudaGetSymbolAddress((void**)&x,   g_x);
    cudaGetSymbolAddress((void**)&q,   g_q);
    cudaGetSymbolAddress((void**)&k,   g_k);
    cudaGetSymbolAddress((void**)&v,   g_v);
    cudaGetSymbolAddress((void**)&att, g_att);
    cudaGetSymbolAddress((void**)&ff,  g_ff);
    cudaGetSymbolAddress((void**)&w,   g_w);

    const int SMEM_ATTN = 3 * 64 * 65 * (int)sizeof(float);
    const int SMEM_G128 = (3 * 128 * 20 + 3 * 2048) * 4;  // 55296
    const int SMEM_G64  = (3 * 64 * 20 + 3 * 2048) * 4;   // 39936
    cudaFuncSetAttribute(attn_kernel, cudaFuncAttributeMaxDynamicSharedMemorySize, SMEM_ATTN);
    cudaFuncSetAttribute(gemm_mma<0, 128>, cudaFuncAttributeMaxDynamicSharedMemorySize, SMEM_G128);
    cudaFuncSetAttribute(gemm_mma<1, 128>, cudaFuncAttributeMaxDynamicSharedMemorySize, SMEM_G128);
    cudaFuncSetAttribute(gemm_mma<0, 64>,  cudaFuncAttributeMaxDynamicSharedMemorySize, SMEM_G64);
    cudaFuncSetAttribute(gemm_qkv, cudaFuncAttributeMaxDynamicSharedMemorySize, SMEM_G128);

    // Pre-convert all weights to tf32-rounded fp32
    cvt_kernel<<<592, 256>>>(wq,    w + OQ,  (int)(PW / 4));
    cvt_kernel<<<592, 256>>>(wk,    w + OKw, (int)(PW / 4));
    cvt_kernel<<<592, 256>>>(wv,    w + OVw, (int)(PW / 4));
    cvt_kernel<<<592, 256>>>(wo,    w + OOw, (int)(PW / 4));
    cvt_kernel<<<592, 256>>>(w1,    w + O1w, (int)(PF / 4));
    cvt_kernel<<<592, 256>>>(w2,    w + O2w, (int)(PF / 4));
    cvt_kernel<<<592, 256>>>(headw, w + OHw, (int)((size_t)CD * CV / 4));

    embed_kernel<<<(CM * CD + 255) / 256, 256>>>(ids, emb, pe, x);

    dim3 gQKV(CM / 128, CD / 128, 3);   // 288
    dim3 gP64(CM / 64,  CD / 128);      // 192
    dim3 gF1 (CM / 128, CF / 128);      // 384
    dim3 gH  (CM / 128, CV / 128);      // 4000

    for (int l = 0; l < CL; l++) {
        size_t wOff = (size_t)l * CD * CD;
        gemm_qkv<<<gQKV, 256, SMEM_G128>>>(x, w + OQ + wOff, w + OKw + wOff, w + OVw + wOff,
                                           bq + l * CD, bk + l * CD, bv + l * CD, q, k, v);
        attn_kernel<<<dim3(CS / 64, CH, CB), 256, SMEM_ATTN>>>(q, k, v, att);
        gemm_mma<0, 64><<<gP64, 256, SMEM_G64>>>(att, w + OOw + wOff, bo + l * CD, q, CD, CD);
        ln_kernel<<<CM, 256>>>(x, q, ln1g + l * CD, ln1b + l * CD, x);
        gemm_mma<1, 128><<<gF1, 256, SMEM_G128>>>(x, w + O1w + (size_t)l * CD * CF,
                                                  b1 + l * CF, ff, CF, CD);
        gemm_mma<0, 64><<<gP64, 256, SMEM_G64>>>(ff, w + O2w + (size_t)l * CF * CD,
                                                 b2 + l * CD, q, CD, CF);
        ln_kernel<<<CM, 256>>>(x, q, ln2g + l * CD, ln2b + l * CD, x);
    }

    ln_kernel<<<CM, 256>>>(x, nullptr, lnfg, lnfb, q);
    gemm_mma<0, 128><<<gH, 256, SMEM_G128>>>(q, w + OHw, headb, out, CV, CD);
}

// round 8
// speedup vs baseline: 3.6171x; 1.9906x over previous
#include <cuda_runtime.h>
#include <math.h>
#include <stdint.h>

// Model constants
constexpr int CD  = 768;
constexpr int CS  = 1024;
constexpr int CB  = 2;
constexpr int CM  = CB * CS;  // 2048
constexpr int CH  = 12;
constexpr int CHD = 64;
constexpr int CL  = 6;
constexpr int CF  = 3072;
constexpr int CV  = 32000;

// Scratch
__device__ float g_x  [CM * CD];
__device__ float g_q  [CM * CD];
__device__ float g_k  [CM * CD];
__device__ float g_v  [CM * CD];
__device__ float g_att[CM * CD];
__device__ float g_ff [CM * CF];

// Pre-converted (tf32-rounded) weights
constexpr size_t PW   = (size_t)CL * CD * CD;
constexpr size_t PF   = (size_t)CL * CD * CF;
constexpr size_t OQ   = 0;
constexpr size_t OKw  = PW;
constexpr size_t OVw  = 2 * PW;
constexpr size_t OOw  = 3 * PW;
constexpr size_t O1w  = 4 * PW;
constexpr size_t O2w  = 4 * PW + PF;
constexpr size_t OHw  = 4 * PW + 2 * PF;
constexpr size_t WTOT = 4 * PW + 2 * PF + (size_t)CD * CV;
__device__ float g_w[WTOT];

// Single extern shared symbol, cast per-kernel
extern __shared__ char s_raw[];

// ---------------------------------------------------------------------------
// Helpers
// ---------------------------------------------------------------------------
__device__ __forceinline__ uint32_t f2tf(float f) {
    uint32_t u;
    asm("cvt.rna.tf32.f32 %0, %1;" : "=r"(u) : "f"(f));
    return u;
}
__device__ __forceinline__ void mma_tf32(float* c, const uint32_t* a, const uint32_t* b) {
    asm volatile(
        "mma.sync.aligned.m16n8k8.row.col.f32.tf32.tf32.f32 "
        "{%0,%1,%2,%3}, {%4,%5,%6,%7}, {%8,%9}, {%0,%1,%2,%3};"
        : "+f"(c[0]), "+f"(c[1]), "+f"(c[2]), "+f"(c[3])
        : "r"(a[0]), "r"(a[1]), "r"(a[2]), "r"(a[3]), "r"(b[0]), "r"(b[1]));
}
#define CP_ASYNC16(dst, src) \
    asm volatile("cp.async.ca.shared.global [%0], [%1], 16;" :: "r"(dst), "l"(src))
#define CP_COMMIT() asm volatile("cp.async.commit_group;")
#define CP_WAIT1()  asm volatile("cp.async.wait_group 1;")

// ---------------------------------------------------------------------------
// Weight conversion (fp32 -> tf32-rounded fp32)
// ---------------------------------------------------------------------------
__global__ void cvt_kernel(const float* __restrict__ src, float* __restrict__ dst, int n4) {
    int i = blockIdx.x * blockDim.x + threadIdx.x;
    int stride = gridDim.x * blockDim.x;
    for (; i < n4; i += stride) {
        float4 v = *(const float4*)(src + (size_t)i * 4);
        uint4 u;
        u.x = f2tf(v.x);
        u.y = f2tf(v.y);
        u.z = f2tf(v.z);
        u.w = f2tf(v.w);
        *(uint4*)(dst + (size_t)i * 4) = u;
    }
}

// ---------------------------------------------------------------------------
// Embedding
// ---------------------------------------------------------------------------
__global__ void embed_kernel(const int* __restrict__ ids, const float* __restrict__ emb,
                             const float* __restrict__ pe, float* __restrict__ out) {
    int idx = blockIdx.x * blockDim.x + threadIdx.x;
    if (idx >= CM * CD) return;
    int r = idx / CD;
    int d = idx - r * CD;
    int s = r & (CS - 1);
    out[idx] = emb[ids[r] * CD + d] * 27.712812921102035f + pe[s * CD + d];
}

// ---------------------------------------------------------------------------
// tf32 mma.sync GEMM core (unchanged from R7)
// ---------------------------------------------------------------------------
template <int ACT, int BM>
__device__ __forceinline__ void gemm_core(const float* __restrict__ A,
                                          const float* __restrict__ B,
                                          const float* __restrict__ bias,
                                          float* __restrict__ C,
                                          int N, int K, int r0, int c0,
                                          uint32_t* sm) {
    constexpr int AW  = 20;
    constexpr int SA  = BM * AW;
    constexpr int SB  = 16 * 128;
    constexpr int ABo = 3 * SA;
    constexpr int AIT = BM / 64;
    constexpr int MT  = BM / 32;

    const int tid  = threadIdx.x;
    const int lane = tid & 31;
    const int wid  = tid >> 5;
    const int wr   = wid >> 2;
    const int wc   = wid & 3;
    const int lr   = lane >> 2;
    const int lc   = lane & 3;
    const int NK   = K >> 4;

    const float* Ag = A + (size_t)r0 * K;
    const float* Bg = B + c0;
    const uint32_t smb = (uint32_t)__cvta_generic_to_shared(sm);

    float cc[MT][4][4];
#pragma unroll
    for (int mt = 0; mt < MT; mt++)
#pragma unroll
        for (int nt = 0; nt < 4; nt++)
#pragma unroll
            for (int j = 0; j < 4; j++) cc[mt][nt][j] = 0.0f;

    int am[AIT], ak[AIT];
#pragma unroll
    for (int it = 0; it < AIT; it++) {
        int i = tid + it * 256;
        am[it] = i >> 2;
        ak[it] = (i & 3) << 2;
    }

    float4 rA[2][AIT];

#pragma unroll
    for (int s = 0; s < 2; s++)
#pragma unroll
        for (int it = 0; it < AIT; it++)
            rA[s][it] = *(const float4*)(Ag + (size_t)am[it] * K + s * 16 + ak[it]);

#pragma unroll
    for (int s = 0; s < 2; s++) {
#pragma unroll
        for (int g2 = 0; g2 < 2; g2++) {
            int g = tid + g2 * 256;
            int k = g >> 5, n4 = (g & 31) << 2;
            uint32_t dst = smb + 4u * (ABo + s * SB + k * 128 + (n4 ^ ((k & 3) << 3)));
            CP_ASYNC16(dst, Bg + (size_t)(s * 16 + k) * N + n4);
        }
        CP_COMMIT();
    }
#pragma unroll
    for (int it = 0; it < AIT; it++) {
        uint4 v;
        v.x = f2tf(rA[0][it].x);
        v.y = f2tf(rA[0][it].y);
        v.z = f2tf(rA[0][it].z);
        v.w = f2tf(rA[0][it].w);
        *(uint4*)&sm[am[it] * AW + ak[it]] = v;
    }

#pragma unroll 1
    for (int j = 0; j < NK; j++) {
        CP_WAIT1();
        __syncthreads();

        if (j + 2 < NK) {
#pragma unroll
            for (int g2 = 0; g2 < 2; g2++) {
                int g = tid + g2 * 256;
                int k = g >> 5, n4 = (g & 31) << 2;
                uint32_t dst = smb + 4u * (ABo + ((j + 2) % 3) * SB + k * 128 +
                                           (n4 ^ ((k & 3) << 3)));
                CP_ASYNC16(dst, Bg + (size_t)((j + 2) * 16 + k) * N + n4);
            }
        }
        CP_COMMIT();

        if (j + 1 < NK) {
            uint32_t* As1 = sm + ((j + 1) % 3) * SA;
#pragma unroll
            for (int it = 0; it < AIT; it++) {
                uint4 v;
                v.x = f2tf(rA[(j + 1) & 1][it].x);
                v.y = f2tf(rA[(j + 1) & 1][it].y);
                v.z = f2tf(rA[(j + 1) & 1][it].z);
                v.w = f2tf(rA[(j + 1) & 1][it].w);
                *(uint4*)&As1[am[it] * AW + ak[it]] = v;
            }
        }
        if (j + 2 < NK) {
#pragma unroll
            for (int it = 0; it < AIT; it++)
                rA[j & 1][it] = *(const float4*)(Ag + (size_t)am[it] * K + (j + 2) * 16 + ak[it]);
        }

        const uint32_t* As_ = sm + (j % 3) * SA;
        const uint32_t* Bs_ = sm + ABo + (j % 3) * SB;
#pragma unroll
        for (int ks = 0; ks < 2; ks++) {
            const int k0 = ks * 8 + lc;
            uint32_t af[MT][4], bf[4][2];
#pragma unroll
            for (int mt = 0; mt < MT; mt++) {
                int m = wr * (BM / 2) + mt * 16 + lr;
                af[mt][0] = As_[m * AW + k0];
                af[mt][1] = As_[(m + 8) * AW + k0];
                af[mt][2] = As_[m * AW + k0 + 4];
                af[mt][3] = As_[(m + 8) * AW + k0 + 4];
            }
#pragma unroll
            for (int nt = 0; nt < 4; nt++) {
                int n = wc * 32 + nt * 8 + lr;
                bf[nt][0] = Bs_[k0 * 128 + (n ^ ((k0 & 3) << 3))];
                bf[nt][1] = Bs_[(k0 + 4) * 128 + (n ^ (((k0 + 4) & 3) << 3))];
            }
#pragma unroll
            for (int mt = 0; mt < MT; mt++)
#pragma unroll
                for (int nt = 0; nt < 4; nt++) mma_tf32(cc[mt][nt], af[mt], bf[nt]);
        }
    }

#pragma unroll
    for (int nt = 0; nt < 4; nt++) {
        int col = c0 + wc * 32 + nt * 8 + 2 * lc;
        float b0 = bias[col], b1 = bias[col + 1];
#pragma unroll
        for (int mt = 0; mt < MT; mt++) {
            int rlo = r0 + wr * (BM / 2) + mt * 16 + lr;
            float o0 = cc[mt][nt][0] + b0;
            float o1 = cc[mt][nt][1] + b1;
            float o2 = cc[mt][nt][2] + b0;
            float o3 = cc[mt][nt][3] + b1;
            if (ACT == 1) {
                o0 = 0.5f * o0 * (1.0f + erff(o0 * 0.70710678118654752f));
                o1 = 0.5f * o1 * (1.0f + erff(o1 * 0.70710678118654752f));
                o2 = 0.5f * o2 * (1.0f + erff(o2 * 0.70710678118654752f));
                o3 = 0.5f * o3 * (1.0f + erff(o3 * 0.70710678118654752f));
            }
            *(float2*)&C[(size_t)rlo * N + col]       = make_float2(o0, o1);
            *(float2*)&C[(size_t)(rlo + 8) * N + col] = make_float2(o2, o3);
        }
    }
}

template <int ACT, int BM>
__global__ void __launch_bounds__(256, 2) gemm_mma(const float* __restrict__ A,
                                                   const float* __restrict__ B,
                                                   const float* __restrict__ bias,
                                                   float* __restrict__ C, int N, int K) {
    gemm_core<ACT, BM>(A, B, bias, C, N, K, blockIdx.x * BM, blockIdx.y * 128,
                       (uint32_t*)s_raw);
}

__global__ void __launch_bounds__(256, 2) gemm_qkv(const float* __restrict__ A,
                                                   const float* __restrict__ Bq,
                                                   const float* __restrict__ Bk,
                                                   const float* __restrict__ Bv,
                                                   const float* __restrict__ bq,
                                                   const float* __restrict__ bk,
                                                   const float* __restrict__ bv,
                                                   float* __restrict__ Cq,
                                                   float* __restrict__ Ck,
                                                   float* __restrict__ Cv) {
    const float* B;
    const float* bi;
    float* C;
    if (blockIdx.z == 0)      { B = Bq; bi = bq; C = Cq; }
    else if (blockIdx.z == 1) { B = Bk; bi = bk; C = Ck; }
    else                      { B = Bv; bi = bv; C = Cv; }
    gemm_core<0, 128>(A, B, bi, C, CD, CD, blockIdx.x * 128, blockIdx.y * 128,
                      (uint32_t*)s_raw);
}

// ---------------------------------------------------------------------------
// Tensor-core causal flash attention (tf32 mma.sync)
// CTA: 128 q rows x (head, batch); 8 warps, 16 rows each. K/V tiles 64x64
// double-buffered via cp.async. P converted via per-warp smem buffer.
// smem (words): [0,9728) P (8w x 16 x 76) union Q[128][68];
//               [9728,+2*4352) K stages [64][68]; then 2*4608 V stages [64][72].
// ---------------------------------------------------------------------------
__global__ void __launch_bounds__(256, 1) attn_mma(const float* __restrict__ q,
                                                   const float* __restrict__ k,
                                                   const float* __restrict__ v,
                                                   float* __restrict__ o) {
    float* sm = (float*)s_raw;
    constexpr int QW = 68, PWD = 76, KW = 68, VW = 72;
    constexpr int OFF_K = 9728;
    constexpr int KSTG  = 64 * KW;            // 4352
    constexpr int OFF_V = OFF_K + 2 * KSTG;   // 18432
    constexpr int VSTG  = 64 * VW;            // 4608

    const int tid = threadIdx.x, lane = tid & 31, wid = tid >> 5;
    const int g = lane >> 2, t = lane & 3;
    const int qt = (int)(gridDim.x - 1 - blockIdx.x);
    const int h = blockIdx.y, b = blockIdx.z;
    const int qbase = qt * 128;
    const int rowoff = b * CS;
    const int hd = h * CHD;
    const int nkt = 2 * qt + 2;
    const uint32_t smb = (uint32_t)__cvta_generic_to_shared(sm);

    // Stage Q [128][68], pre-scaled
#pragma unroll
    for (int it = 0; it < 8; it++) {
        int i = tid + it * 256;
        int r = i >> 4, c = (i & 15) << 2;
        float4 qv = *(const float4*)(q + (size_t)(rowoff + qbase + r) * CD + hd + c);
        qv.x *= 0.125f; qv.y *= 0.125f; qv.z *= 0.125f; qv.w *= 0.125f;
        *(float4*)(sm + r * QW + c) = qv;
    }
    // Start K/V tile 0
#pragma unroll
    for (int j = 0; j < 4; j++) {
        int i = tid + j * 256;
        int r = i >> 4, c = (i & 15) << 2;
        CP_ASYNC16(smb + 4u * (OFF_K + r * KW + c),
                   k + (size_t)(rowoff + r) * CD + hd + c);
        CP_ASYNC16(smb + 4u * (OFF_V + r * VW + c),
                   v + (size_t)(rowoff + r) * CD + hd + c);
    }
    CP_COMMIT();
    __syncthreads();

    // Q fragments (register-resident for whole CTA)
    uint32_t qf[8][4];
    {
        int r0 = wid * 16 + g;
#pragma unroll
        for (int kk = 0; kk < 8; kk++) {
            qf[kk][0] = f2tf(sm[r0 * QW + kk * 8 + t]);
            qf[kk][1] = f2tf(sm[(r0 + 8) * QW + kk * 8 + t]);
            qf[kk][2] = f2tf(sm[r0 * QW + kk * 8 + t + 4]);
            qf[kk][3] = f2tf(sm[(r0 + 8) * QW + kk * 8 + t + 4]);
        }
    }

    float m0 = -1e30f, m1 = -1e30f, l0 = 0.0f, l1 = 0.0f;
    float o_[8][4];
#pragma unroll
    for (int nt = 0; nt < 8; nt++)
#pragma unroll
        for (int j = 0; j < 4; j++) o_[nt][j] = 0.0f;

    const int wrow = qbase + wid * 16;

#pragma unroll 1
    for (int kt = 0; kt < nkt; kt++) {
        const int s = kt & 1;
        __syncthreads();  // all warps done with stage s^1 and Q/P region
        if (kt + 1 < nkt) {
#pragma unroll
            for (int j = 0; j < 4; j++) {
                int i = tid + j * 256;
                int r = i >> 4, c = (i & 15) << 2;
                CP_ASYNC16(smb + 4u * (OFF_K + (s ^ 1) * KSTG + r * KW + c),
                           k + (size_t)(rowoff + (kt + 1) * 64 + r) * CD + hd + c);
                CP_ASYNC16(smb + 4u * (OFF_V + (s ^ 1) * VSTG + r * VW + c),
                           v + (size_t)(rowoff + (kt + 1) * 64 + r) * CD + hd + c);
            }
        }
        CP_COMMIT();
        CP_WAIT1();
        __syncthreads();

        if (kt * 64 > wrow + 15) continue;  // fully masked for this warp

        const float* Ks = sm + OFF_K + s * KSTG;
        const float* Vs = sm + OFF_V + s * VSTG;

        // S = Q K^T
        float c_[8][4];
#pragma unroll
        for (int nt = 0; nt < 8; nt++)
#pragma unroll
            for (int j = 0; j < 4; j++) c_[nt][j] = 0.0f;
#pragma unroll
        for (int kk = 0; kk < 8; kk++) {
#pragma unroll
            for (int nt = 0; nt < 8; nt++) {
                uint32_t bf[2];
                bf[0] = f2tf(Ks[(nt * 8 + g) * KW + kk * 8 + t]);
                bf[1] = f2tf(Ks[(nt * 8 + g) * KW + kk * 8 + t + 4]);
                mma_tf32(c_[nt], qf[kk], bf);
            }
        }

        // Causal mask (diagonal-overlap tiles only)
        if (kt * 64 + 63 > wrow) {
            int r0g = wrow + g, r1g = r0g + 8;
#pragma unroll
            for (int nt = 0; nt < 8; nt++) {
                int col = kt * 64 + nt * 8 + 2 * t;
                if (col     > r0g) c_[nt][0] = -1e9f;
                if (col + 1 > r0g) c_[nt][1] = -1e9f;
                if (col     > r1g) c_[nt][2] = -1e9f;
                if (col + 1 > r1g) c_[nt][3] = -1e9f;
            }
        }

        // Online softmax
        float tm0 = c_[0][0], tm1 = c_[0][2];
#pragma unroll
        for (int nt = 0; nt < 8; nt++) {
            tm0 = fmaxf(tm0, fmaxf(c_[nt][0], c_[nt][1]));
            tm1 = fmaxf(tm1, fmaxf(c_[nt][2], c_[nt][3]));
        }
        tm0 = fmaxf(tm0, __shfl_xor_sync(0xffffffffu, tm0, 1));
        tm0 = fmaxf(tm0, __shfl_xor_sync(0xffffffffu, tm0, 2));
        tm1 = fmaxf(tm1, __shfl_xor_sync(0xffffffffu, tm1, 1));
        tm1 = fmaxf(tm1, __shfl_xor_sync(0xffffffffu, tm1, 2));

        float mn0 = fmaxf(m0, tm0), mn1 = fmaxf(m1, tm1);
        float al0 = __expf(m0 - mn0), al1 = __expf(m1 - mn1);
        float ls0 = 0.0f, ls1 = 0.0f;
#pragma unroll
        for (int nt = 0; nt < 8; nt++) {
            c_[nt][0] = __expf(c_[nt][0] - mn0);
            c_[nt][1] = __expf(c_[nt][1] - mn0);
            c_[nt][2] = __expf(c_[nt][2] - mn1);
            c_[nt][3] = __expf(c_[nt][3] - mn1);
            ls0 += c_[nt][0] + c_[nt][1];
            ls1 += c_[nt][2] + c_[nt][3];
        }
        ls0 += __shfl_xor_sync(0xffffffffu, ls0, 1);
        ls0 += __shfl_xor_sync(0xffffffffu, ls0, 2);
        ls1 += __shfl_xor_sync(0xffffffffu, ls1, 1);
        ls1 += __shfl_xor_sync(0xffffffffu, ls1, 2);
        l0 = l0 * al0 + ls0; m0 = mn0;
        l1 = l1 * al1 + ls1; m1 = mn1;
#pragma unroll
        for (int nt = 0; nt < 8; nt++) {
            o_[nt][0] *= al0; o_[nt][1] *= al0;
            o_[nt][2] *= al1; o_[nt][3] *= al1;
        }

        // P -> per-warp smem (tf32-rounded), then reload as A fragments
        float* Pw = sm + wid * 16 * PWD;
#pragma unroll
        for (int nt = 0; nt < 8; nt++) {
            int cc0 = nt * 8 + 2 * t;
            Pw[g * PWD + cc0]           = __uint_as_float(f2tf(c_[nt][0]));
            Pw[g * PWD + cc0 + 1]       = __uint_as_float(f2tf(c_[nt][1]));
            Pw[(g + 8) * PWD + cc0]     = __uint_as_float(f2tf(c_[nt][2]));
            Pw[(g + 8) * PWD + cc0 + 1] = __uint_as_float(f2tf(c_[nt][3]));
        }
        __syncwarp();

        // O += P V
#pragma unroll
        for (int kk = 0; kk < 8; kk++) {
            uint32_t af[4];
            af[0] = __float_as_uint(Pw[g * PWD + kk * 8 + t]);
            af[1] = __float_as_uint(Pw[(g + 8) * PWD + kk * 8 + t]);
            af[2] = __float_as_uint(Pw[g * PWD + kk * 8 + t + 4]);
            af[3] = __float_as_uint(Pw[(g + 8) * PWD + kk * 8 + t + 4]);
#pragma unroll
            for (int nt = 0; nt < 8; nt++) {
                uint32_t bf[2];
                bf[0] = f2tf(Vs[(kk * 8 + t) * VW + nt * 8 + g]);
                bf[1] = f2tf(Vs[(kk * 8 + t + 4) * VW + nt * 8 + g]);
                mma_tf32(o_[nt], af, bf);
            }
        }
        __syncwarp();
    }

    float i0 = 1.0f / l0, i1 = 1.0f / l1;
    int row0 = rowoff + qbase + wid * 16 + g;
#pragma unroll
    for (int nt = 0; nt < 8; nt++) {
        int col = hd + nt * 8 + 2 * t;
        *(float2*)&o[(size_t)row0 * CD + col] = make_float2(o_[nt][0] * i0, o_[nt][1] * i0);
        *(float2*)&o[(size_t)(row0 + 8) * CD + col] = make_float2(o_[nt][2] * i1, o_[nt][3] * i1);
    }
}

// ---------------------------------------------------------------------------
// LayerNorm
// ---------------------------------------------------------------------------
__global__ void ln_kernel(const float* __restrict__ x, const float* __restrict__ res,
                          const float* __restrict__ g, const float* __restrict__ b,
                          float* __restrict__ out) {
    int r = blockIdx.x, t = threadIdx.x;
    __shared__ float red[8];
    int base = r * CD;
    float a0 = x[base + t], a1 = x[base + t + 256], a2 = x[base + t + 512];
    if (res) {
        a0 += res[base + t];
        a1 += res[base + t + 256];
        a2 += res[base + t + 512];
    }
    float sm = a0 + a1 + a2;
#pragma unroll
    for (int o = 16; o; o >>= 1) sm += __shfl_xor_sync(0xffffffffu, sm, o);
    if ((t & 31) == 0) red[t >> 5] = sm;
    __syncthreads();
    float mean = (red[0] + red[1] + red[2] + red[3] + red[4] + red[5] + red[6] + red[7]) *
                 (1.0f / CD);
    __syncthreads();
    float d0 = a0 - mean, d1 = a1 - mean, d2 = a2 - mean;
    float vs = d0 * d0 + d1 * d1 + d2 * d2;
#pragma unroll
    for (int o = 16; o; o >>= 1) vs += __shfl_xor_sync(0xffffffffu, vs, o);
    if ((t & 31) == 0) red[t >> 5] = vs;
    __syncthreads();
    float var = (red[0] + red[1] + red[2] + red[3] + red[4] + red[5] + red[6] + red[7]) *
                (1.0f / CD);
    float rstd = rsqrtf(var + 1e-5f);
    out[base + t]       = d0 * rstd * g[t]       + b[t];
    out[base + t + 256] = d1 * rstd * g[t + 256] + b[t + 256];
    out[base + t + 512] = d2 * rstd * g[t + 512] + b[t + 512];
}

// ---------------------------------------------------------------------------
// Launch
// ---------------------------------------------------------------------------
extern "C" void kernel_launch(void* const* d_in, const int* in_sizes, int n_in,
                              void* d_out, int out_size) {
    const int*   ids   = (const int*)  d_in[0];
    const float* emb   = (const float*)d_in[1];
    const float* pe    = (const float*)d_in[2];
    const float* wq    = (const float*)d_in[3];
    const float* bq    = (const float*)d_in[4];
    const float* wk    = (const float*)d_in[5];
    const float* bk    = (const float*)d_in[6];
    const float* wv    = (const float*)d_in[7];
    const float* bv    = (const float*)d_in[8];
    const float* wo    = (const float*)d_in[9];
    const float* bo    = (const float*)d_in[10];
    const float* ln1g  = (const float*)d_in[11];
    const float* ln1b  = (const float*)d_in[12];
    const float* w1    = (const float*)d_in[13];
    const float* b1    = (const float*)d_in[14];
    const float* w2    = (const float*)d_in[15];
    const float* b2    = (const float*)d_in[16];
    const float* ln2g  = (const float*)d_in[17];
    const float* ln2b  = (const float*)d_in[18];
    const float* lnfg  = (const float*)d_in[19];
    const float* lnfb  = (const float*)d_in[20];
    const float* headw = (const float*)d_in[21];
    const float* headb = (const float*)d_in[22];
    float* out = (float*)d_out;

    float *x, *q, *k, *v, *att, *ff, *w;
    cudaGetSymbolAddress((void**)&x,   g_x);
    cudaGetSymbolAddress((void**)&q,   g_q);
    cudaGetSymbolAddress((void**)&k,   g_k);
    cudaGetSymbolAddress((void**)&v,   g_v);
    cudaGetSymbolAddress((void**)&att, g_att);
    cudaGetSymbolAddress((void**)&ff,  g_ff);
    cudaGetSymbolAddress((void**)&w,   g_w);

    const int SMEM_ATTN = (9728 + 2 * 4352 + 2 * 4608) * 4;  // 110592
    const int SMEM_G128 = (3 * 128 * 20 + 3 * 2048) * 4;     // 55296
    const int SMEM_G64  = (3 * 64 * 20 + 3 * 2048) * 4;      // 39936
    cudaFuncSetAttribute(attn_mma, cudaFuncAttributeMaxDynamicSharedMemorySize, SMEM_ATTN);
    cudaFuncSetAttribute(gemm_mma<0, 128>, cudaFuncAttributeMaxDynamicSharedMemorySize, SMEM_G128);
    cudaFuncSetAttribute(gemm_mma<1, 128>, cudaFuncAttributeMaxDynamicSharedMemorySize, SMEM_G128);
    cudaFuncSetAttribute(gemm_mma<0, 64>,  cudaFuncAttributeMaxDynamicSharedMemorySize, SMEM_G64);
    cudaFuncSetAttribute(gemm_qkv, cudaFuncAttributeMaxDynamicSharedMemorySize, SMEM_G128);

    // Pre-convert all weights to tf32-rounded fp32
    cvt_kernel<<<592, 256>>>(wq,    w + OQ,  (int)(PW / 4));
    cvt_kernel<<<592, 256>>>(wk,    w + OKw, (int)(PW / 4));
    cvt_kernel<<<592, 256>>>(wv,    w + OVw, (int)(PW / 4));
    cvt_kernel<<<592, 256>>>(wo,    w + OOw, (int)(PW / 4));
    cvt_kernel<<<592, 256>>>(w1,    w + O1w, (int)(PF / 4));
    cvt_kernel<<<592, 256>>>(w2,    w + O2w, (int)(PF / 4));
    cvt_kernel<<<592, 256>>>(headw, w + OHw, (int)((size_t)CD * CV / 4));

    embed_kernel<<<(CM * CD + 255) / 256, 256>>>(ids, emb, pe, x);

    dim3 gQKV(CM / 128, CD / 128, 3);   // 288
    dim3 gP64(CM / 64,  CD / 128);      // 192
    dim3 gF1 (CM / 128, CF / 128);      // 384
    dim3 gH  (CM / 128, CV / 128);      // 4000
    dim3 gATT(CS / 128, CH, CB);        // 192

    for (int l = 0; l < CL; l++) {
        size_t wOff = (size_t)l * CD * CD;
        gemm_qkv<<<gQKV, 256, SMEM_G128>>>(x, w + OQ + wOff, w + OKw + wOff, w + OVw + wOff,
                                           bq + l * CD, bk + l * CD, bv + l * CD, q, k, v);
        attn_mma<<<gATT, 256, SMEM_ATTN>>>(q, k, v, att);
        gemm_mma<0, 64><<<gP64, 256, SMEM_G64>>>(att, w + OOw + wOff, bo + l * CD, q, CD, CD);
        ln_kernel<<<CM, 256>>>(x, q, ln1g + l * CD, ln1b + l * CD, x);
        gemm_mma<1, 128><<<gF1, 256, SMEM_G128>>>(x, w + O1w + (size_t)l * CD * CF,
                                                  b1 + l * CF, ff, CF, CD);
        gemm_mma<0, 64><<<gP64, 256, SMEM_G64>>>(ff, w + O2w + (size_t)l * CF * CD,
                                                 b2 + l * CD, q, CD, CF);
        ln_kernel<<<CM, 256>>>(x, q, ln2g + l * CD, ln2b + l * CD, x);
    }

    ln_kernel<<<CM, 256>>>(x, nullptr, lnfg, lnfb, q);
    gemm_mma<0, 128><<<gH, 256, SMEM_G128>>>(q, w + OHw, headb, out, CV, CD);
}